// round 12
// baseline (speedup 1.0000x reference)
#include <cuda_runtime.h>

#define N_NODES 100000
#define N_EDGES 1000000
#define D 64
#define CAP 64   // max in-edges per node (Poisson(10): P(>64) negligible)

typedef unsigned long long u64;

// Static scratch
__device__ __align__(16) float g_agg[N_NODES * D];          // 25.6 MB
__device__ int g_deg[N_NODES];
__device__ u64 g_list[(size_t)N_NODES * CAP];               // 51.2 MB
__device__ __align__(16) float g_wdup[D * 2 * D];           // 32 KB: [k][2j] = W[j][k] duplicated

// ---------------------------------------------------------------------------
// Build step 1: zero degree counters
// ---------------------------------------------------------------------------
__global__ void zero_deg_kernel() {
    int i = blockIdx.x * blockDim.x + threadIdx.x;
    if (i < N_NODES) g_deg[i] = 0;
}

// ---------------------------------------------------------------------------
// Build step 1b: duplicate-transpose W into g_wdup[k][2j] = (W[j][k], W[j][k])
// ---------------------------------------------------------------------------
__global__ void wdup_kernel(const float* __restrict__ W) {
    int i = blockIdx.x * blockDim.x + threadIdx.x;   // 0..4095
    if (i < D * D) {
        int j = i >> 6;
        int k = i & 63;
        float w = W[i];
        g_wdup[k * 128 + 2 * j]     = w;
        g_wdup[k * 128 + 2 * j + 1] = w;
    }
}

// ---------------------------------------------------------------------------
// Build step 2: bucket edges by destination, packed (w<<32 | src)
// ---------------------------------------------------------------------------
__global__ void fill_kernel(const int* __restrict__ ei,
                            const float* __restrict__ ew) {
    int e = blockIdx.x * blockDim.x + threadIdx.x;
    if (e >= N_EDGES) return;
    int dst = ei[N_EDGES + e];
    dst = min(max(dst, 0), N_NODES - 1);
    int src = ei[e];
    src = min(max(src, 0), N_NODES - 1);
    float w = ew[e];
    int pos = atomicAdd(&g_deg[dst], 1);
    if (pos < CAP)
        g_list[(size_t)dst * CAP + pos] =
            ((u64)__float_as_uint(w) << 32) | (unsigned)src;
}

// ---------------------------------------------------------------------------
// Aggregate: 2 nodes per warp (half-warps), float4 chunk per lane.
// ---------------------------------------------------------------------------
__global__ void agg_kernel(const float* __restrict__ feat) {
    int warp = blockIdx.x * 4 + (threadIdx.x >> 5);
    int lane = threadIdx.x & 31;
    int h = lane >> 4;
    int c = lane & 15;

    int n_real = warp * 2 + h;
    int n = (n_real < N_NODES) ? n_real : (N_NODES - 1);

    int deg = min(g_deg[n], CAP);
    int degmax = max(deg, __shfl_xor_sync(0xffffffffu, deg, 16));
    const u64* lst = g_list + (size_t)n * CAP;

    float4 acc = *reinterpret_cast<const float4*>(feat + (size_t)n * D + c * 4);

    for (int base = 0; base < degmax; base += 16) {
        int mh = min(16, deg - base);
        int mm = min(16, degmax - base);
        u64 p = (c < mh) ? lst[base + c] : 0ull;
        for (int j = 0; j < mm; j++) {
            u64 pj = __shfl_sync(0xffffffffu, p, (h << 4) | j);
            if (j < mh) {
                int   src = (int)(unsigned)(pj & 0xffffffffu);
                float w   = __uint_as_float((unsigned)(pj >> 32));
                float4 v = *reinterpret_cast<const float4*>(feat + (size_t)src * D + c * 4);
                acc.x += w * v.x; acc.y += w * v.y;
                acc.z += w * v.z; acc.w += w * v.w;
            }
        }
    }

    if (n_real < N_NODES)
        *reinterpret_cast<float4*>(g_agg + (size_t)n * D + c * 4) = acc;
}

// ---------------------------------------------------------------------------
// GEMM: out = agg @ W^T + b, node-paired f32x2 accumulators.
// Block 128 thr, tile 64 nodes x 64 outputs.
//   warp w -> j0 = 16w; lane l -> node pair (l, l+32)
//   As2[k][l] = (agg[n0+l][k], agg[n0+l+32][k])  (stride 33 fl2: conflict-free)
//   Wd[k][2j] = W dup; in-loop W reads are uniform LDS.128 broadcasts
// Per lane-k: 1 LDS.64 + 8 bcast LDS.128 + 16 fma.f32x2  -> FMA-bound.
// ---------------------------------------------------------------------------
__global__ void gemm_kernel(const float* __restrict__ b,
                            float* __restrict__ out) {
    __shared__ float2 As2[64 * 33];              // 16.9 KB
    __shared__ __align__(16) float Wd[64 * 128]; // 32 KB

    int tid = threadIdx.x;          // 0..127
    int n0  = blockIdx.x * 64;

    // Copy g_wdup -> Wd (coalesced float4, conflict-free)
    #pragma unroll
    for (int s = 0; s < 16; s++) {
        int i4 = tid + s * 128;     // 0..2047
        reinterpret_cast<float4*>(Wd)[i4] =
            reinterpret_cast<const float4*>(g_wdup)[i4];
    }

    // Fill As2 interleaved: lane = row r, per-warp kq column group.
    // Row data reused across 16 kq -> L1-resident; STS.64 conflict-free.
    #pragma unroll
    for (int s = 0; s < 4; s++) {
        int r  = tid & 31;
        int kq = (tid >> 5) + s * 4;    // 0..15
        int na = n0 + r;
        int nb = n0 + r + 32;
        na = (na < N_NODES) ? na : (N_NODES - 1);
        nb = (nb < N_NODES) ? nb : (N_NODES - 1);
        float4 v0 = *(reinterpret_cast<const float4*>(g_agg + (size_t)na * D) + kq);
        float4 v1 = *(reinterpret_cast<const float4*>(g_agg + (size_t)nb * D) + kq);
        As2[(4 * kq + 0) * 33 + r] = make_float2(v0.x, v1.x);
        As2[(4 * kq + 1) * 33 + r] = make_float2(v0.y, v1.y);
        As2[(4 * kq + 2) * 33 + r] = make_float2(v0.z, v1.z);
        As2[(4 * kq + 3) * 33 + r] = make_float2(v0.w, v1.w);
    }
    __syncthreads();

    int w  = tid >> 5;
    int l  = tid & 31;
    int j0 = w * 16;

    u64 acc[16];
    #pragma unroll
    for (int m = 0; m < 16; m++) acc[m] = 0ull;

    #pragma unroll 4
    for (int k = 0; k < 64; k++) {
        u64 ap = *reinterpret_cast<const u64*>(&As2[k * 33 + l]);   // (a_l, a_l32)
        const double2* wrow = reinterpret_cast<const double2*>(&Wd[k * 128 + 2 * j0]);
        #pragma unroll
        for (int q = 0; q < 8; q++) {
            double2 wq = wrow[q];
            u64 wp0 = __double_as_longlong(wq.x);   // (w_{j0+2q},   dup)
            u64 wp1 = __double_as_longlong(wq.y);   // (w_{j0+2q+1}, dup)
            asm("fma.rn.f32x2 %0, %1, %2, %0;" : "+l"(acc[2*q+0]) : "l"(ap), "l"(wp0));
            asm("fma.rn.f32x2 %0, %1, %2, %0;" : "+l"(acc[2*q+1]) : "l"(ap), "l"(wp1));
        }
    }

    // Epilogue: unpack node-paired accumulators, add bias, store float4s.
    float f0[16], f1[16];
    #pragma unroll
    for (int m = 0; m < 16; m++) {
        float lo, hi;
        asm("mov.b64 {%0, %1}, %2;" : "=f"(lo), "=f"(hi) : "l"(acc[m]));
        float bias = b[j0 + m];
        f0[m] = lo + bias;
        f1[m] = hi + bias;
    }

    int nA = n0 + l;
    int nB = n0 + l + 32;
    if (nA < N_NODES) {
        float4* op = reinterpret_cast<float4*>(out + (size_t)nA * D + j0);
        #pragma unroll
        for (int q = 0; q < 4; q++)
            op[q] = make_float4(f0[4*q], f0[4*q+1], f0[4*q+2], f0[4*q+3]);
    }
    if (nB < N_NODES) {
        float4* op = reinterpret_cast<float4*>(out + (size_t)nB * D + j0);
        #pragma unroll
        for (int q = 0; q < 4; q++)
            op[q] = make_float4(f1[4*q], f1[4*q+1], f1[4*q+2], f1[4*q+3]);
    }
}

extern "C" void kernel_launch(void* const* d_in, const int* in_sizes, int n_in,
                              void* d_out, int out_size) {
    const float* feat = nullptr;
    const int*   ei   = nullptr;
    const float* ew   = nullptr;
    const float* W    = nullptr;
    const float* b    = nullptr;

    for (int i = 0; i < n_in; i++) {
        switch (in_sizes[i]) {
            case N_NODES * D:   feat = (const float*)d_in[i]; break;
            case 2 * N_EDGES:   ei   = (const int*)d_in[i];   break;
            case N_EDGES:       ew   = (const float*)d_in[i]; break;
            case D * D:         W    = (const float*)d_in[i]; break;
            case D:             b    = (const float*)d_in[i]; break;
            default: break;
        }
    }

    float* out = (float*)d_out;

    zero_deg_kernel<<<(N_NODES + 255) / 256, 256>>>();
    wdup_kernel<<<(D * D + 255) / 256, 256>>>(W);
    fill_kernel<<<(N_EDGES + 255) / 256, 256>>>(ei, ew);
    agg_kernel<<<(N_NODES + 7) / 8, 128>>>(feat);
    gemm_kernel<<<(N_NODES + 63) / 64, 128>>>(b, out);
}

// round 13
// speedup vs baseline: 1.2614x; 1.2614x over previous
#include <cuda_runtime.h>

#define N_NODES 100000
#define N_EDGES 1000000
#define D 64
#define CAP 64   // max in-edges per node (Poisson(10): P(>64) negligible)

typedef unsigned long long u64;

// Static scratch
__device__ __align__(16) float g_agg[N_NODES * D];          // 25.6 MB
__device__ int g_deg[N_NODES];
__device__ u64 g_list[(size_t)N_NODES * CAP];               // 51.2 MB

// ---------------------------------------------------------------------------
// Build step 1: zero degree counters
// ---------------------------------------------------------------------------
__global__ void zero_deg_kernel() {
    int i = blockIdx.x * blockDim.x + threadIdx.x;
    if (i < N_NODES) g_deg[i] = 0;
}

// ---------------------------------------------------------------------------
// Build step 2: bucket edges by destination, packed (w<<32 | src)
// ---------------------------------------------------------------------------
__global__ void fill_kernel(const int* __restrict__ ei,
                            const float* __restrict__ ew) {
    int e = blockIdx.x * blockDim.x + threadIdx.x;
    if (e >= N_EDGES) return;
    int dst = ei[N_EDGES + e];
    dst = min(max(dst, 0), N_NODES - 1);
    int src = ei[e];
    src = min(max(src, 0), N_NODES - 1);
    float w = ew[e];
    int pos = atomicAdd(&g_deg[dst], 1);
    if (pos < CAP)
        g_list[(size_t)dst * CAP + pos] =
            ((u64)__float_as_uint(w) << 32) | (unsigned)src;
}

// ---------------------------------------------------------------------------
// Aggregate: 2 nodes per warp (half-warps), float4 chunk per lane.
// ---------------------------------------------------------------------------
__global__ void agg_kernel(const float* __restrict__ feat) {
    int warp = blockIdx.x * 4 + (threadIdx.x >> 5);
    int lane = threadIdx.x & 31;
    int h = lane >> 4;
    int c = lane & 15;

    int n_real = warp * 2 + h;
    int n = (n_real < N_NODES) ? n_real : (N_NODES - 1);

    int deg = min(g_deg[n], CAP);
    int degmax = max(deg, __shfl_xor_sync(0xffffffffu, deg, 16));
    const u64* lst = g_list + (size_t)n * CAP;

    float4 acc = *reinterpret_cast<const float4*>(feat + (size_t)n * D + c * 4);

    for (int base = 0; base < degmax; base += 16) {
        int mh = min(16, deg - base);
        int mm = min(16, degmax - base);
        u64 p = (c < mh) ? lst[base + c] : 0ull;
        for (int j = 0; j < mm; j++) {
            u64 pj = __shfl_sync(0xffffffffu, p, (h << 4) | j);
            if (j < mh) {
                int   src = (int)(unsigned)(pj & 0xffffffffu);
                float w   = __uint_as_float((unsigned)(pj >> 32));
                float4 v = *reinterpret_cast<const float4*>(feat + (size_t)src * D + c * 4);
                acc.x += w * v.x; acc.y += w * v.y;
                acc.z += w * v.z; acc.w += w * v.w;
            }
        }
    }

    if (n_real < N_NODES)
        *reinterpret_cast<float4*>(g_agg + (size_t)n * D + c * 4) = acc;
}

// ---------------------------------------------------------------------------
// GEMM: out = agg @ W^T + b via even/odd-k-paired fma.rn.f32x2.
// Each f32x2 acc holds (sum over even k, sum over odd k); horizontal add at end.
// Both operands are NATURAL register pairs from float4 LDS.128 — no dup/movs.
//
// Block 256 thr, tile 64 nodes x 64 outputs. Thread (tx,ty):
//   nodes  n = ty + 16i,  outputs j = tx + 16i   (i = 0..3)
// Smem: As4[kq][n ^ (kq&7)], Ws4[kq][j ^ (kq&7)]  (float4 rows over k-quads).
// Per k-quad: 4 A LDS.128 (phase-broadcast) + 4 W LDS.128 (conflict-free:
// per 8-lane phase tx=0..7 -> f4-index mod 8 distinct) + 32 f32x2 FMAs.
// Crossbar ~24 cyc vs FMA 64 cyc per warp-kq -> FMA-bound.
// ---------------------------------------------------------------------------
__global__ void gemm_kernel(const float* __restrict__ W,
                            const float* __restrict__ b,
                            float* __restrict__ out) {
    __shared__ float4 As4[16 * 64];   // 16 KB
    __shared__ float4 Ws4[16 * 64];   // 16 KB

    int tid = threadIdx.x;            // 0..255
    int n0  = blockIdx.x * 64;

    // Fills: coalesced LDG (kq fast), swizzled STS.128 (conflict-free:
    // per phase kq=0..7 with r fixed -> (r^kq) mod 8 distinct).
    {
        int kq = tid & 15;
        int r0 = tid >> 4;            // 0..15
        #pragma unroll
        for (int s = 0; s < 4; s++) {
            int r = r0 + 16 * s;      // 0..63
            int node = n0 + r;
            int src  = (node < N_NODES) ? node : (N_NODES - 1);
            float4 av = *(reinterpret_cast<const float4*>(g_agg + (size_t)src * D) + kq);
            float4 wv = *(reinterpret_cast<const float4*>(W) + r * 16 + kq);
            int col = (r & ~7) | ((r ^ kq) & 7);
            As4[kq * 64 + col] = av;
            Ws4[kq * 64 + col] = wv;
        }
    }
    __syncthreads();

    int tx = tid & 15;
    int ty = tid >> 4;

    u64 acc[4][4];
    #pragma unroll
    for (int i = 0; i < 4; i++)
        #pragma unroll
        for (int j = 0; j < 4; j++)
            acc[i][j] = 0ull;

    #pragma unroll 4
    for (int kq = 0; kq < 16; kq++) {
        int sw = kq & 7;
        float4 a[4], w[4];
        #pragma unroll
        for (int i = 0; i < 4; i++) {
            int cn = ty + 16 * i;
            int cj = tx + 16 * i;
            a[i] = As4[kq * 64 + ((cn & ~7) | ((cn ^ sw) & 7))];
            w[i] = Ws4[kq * 64 + ((cj & ~7) | ((cj ^ sw) & 7))];
        }
        #pragma unroll
        for (int i = 0; i < 4; i++) {
            u64 a01 = __double_as_longlong(reinterpret_cast<const double2&>(a[i]).x);
            u64 a23 = __double_as_longlong(reinterpret_cast<const double2&>(a[i]).y);
            #pragma unroll
            for (int j = 0; j < 4; j++) {
                u64 w01 = __double_as_longlong(reinterpret_cast<const double2&>(w[j]).x);
                u64 w23 = __double_as_longlong(reinterpret_cast<const double2&>(w[j]).y);
                asm("fma.rn.f32x2 %0, %1, %2, %0;" : "+l"(acc[i][j]) : "l"(a01), "l"(w01));
                asm("fma.rn.f32x2 %0, %1, %2, %0;" : "+l"(acc[i][j]) : "l"(a23), "l"(w23));
            }
        }
    }

    // Epilogue: horizontal add (even+odd partial sums) + bias, scalar stores
    // (coalesced across tx).
    float bias[4];
    #pragma unroll
    for (int j = 0; j < 4; j++) bias[j] = b[tx + 16 * j];

    #pragma unroll
    for (int i = 0; i < 4; i++) {
        int node = n0 + ty + 16 * i;
        if (node < N_NODES) {
            float* op = out + (size_t)node * D;
            #pragma unroll
            for (int j = 0; j < 4; j++) {
                float lo, hi;
                asm("mov.b64 {%0, %1}, %2;" : "=f"(lo), "=f"(hi) : "l"(acc[i][j]));
                op[tx + 16 * j] = lo + hi + bias[j];
            }
        }
    }
}

extern "C" void kernel_launch(void* const* d_in, const int* in_sizes, int n_in,
                              void* d_out, int out_size) {
    const float* feat = nullptr;
    const int*   ei   = nullptr;
    const float* ew   = nullptr;
    const float* W    = nullptr;
    const float* b    = nullptr;

    for (int i = 0; i < n_in; i++) {
        switch (in_sizes[i]) {
            case N_NODES * D:   feat = (const float*)d_in[i]; break;
            case 2 * N_EDGES:   ei   = (const int*)d_in[i];   break;
            case N_EDGES:       ew   = (const float*)d_in[i]; break;
            case D * D:         W    = (const float*)d_in[i]; break;
            case D:             b    = (const float*)d_in[i]; break;
            default: break;
        }
    }

    float* out = (float*)d_out;

    zero_deg_kernel<<<(N_NODES + 255) / 256, 256>>>();
    fill_kernel<<<(N_EDGES + 255) / 256, 256>>>(ei, ew);
    agg_kernel<<<(N_NODES + 7) / 8, 128>>>(feat);
    gemm_kernel<<<(N_NODES + 63) / 64, 256>>>(W, b, out);
}